// round 6
// baseline (speedup 1.0000x reference)
#include <cuda_runtime.h>
#include <math.h>

#define NN 100000
#define NE 1600000

// ---------------- scratch (static __device__, no allocation) ----------------
__device__ __align__(16) float g_agg1[(size_t)NN * 128]; // layer-1 neighbor sums -> mean
__device__ __align__(16) float g_cnt[NN];                // in-degree (float)
__device__ __align__(16) float g_h[(size_t)NN * 128];    // layer-1 output (relu)
__device__ __align__(16) float g_tr[(size_t)NN * 80];    // [h@W2l | h@W2r] per node
__device__ __align__(16) float g_agg2[(size_t)NN * 40];  // layer-2 neighbor sums
__device__ __align__(16) float g_w1c[256 * 128];         // [W1l ; W1r] stacked along K
__device__ __align__(16) float g_w2c[128 * 80];          // [W2l | W2r] stacked along N
__device__ int g_is64;                                   // edge_index dtype flag

// ---------------- probe edge_index dtype ----------------
// If the buffer holds int64 (LE, values in [0,1e5)), every odd int32 word is 0.
// For genuine int32 node ids the chance all 128 odd words are 0 is ~0 (and the
// dataset is fixed, so the result is deterministic either way).
__global__ void probe_k(const int* __restrict__ ei32) {
    if (threadIdx.x != 0 || blockIdx.x != 0) return;
    int is64 = 1;
    for (int i = 1; i < 256; i += 2)
        if (ei32[i] != 0) { is64 = 0; break; }
    g_is64 = is64;
}

__device__ __forceinline__ int edge_at(const void* ei, long long idx, int is64) {
    return is64 ? (int)((const long long*)ei)[idx] : ((const int*)ei)[idx];
}

// ---------------- zero scratch ----------------
__global__ void zero_k() {
    int i = blockIdx.x * blockDim.x + threadIdx.x; // NN*32 threads
    if (i < NN * 32) ((float4*)g_agg1)[i] = make_float4(0.f, 0.f, 0.f, 0.f);
    if (i < NN * 10) ((float4*)g_agg2)[i] = make_float4(0.f, 0.f, 0.f, 0.f);
    if (i < NN) g_cnt[i] = 0.f;
}

// ---------------- pack weight matrices ----------------
__global__ void prep_w(const float* __restrict__ W1l, const float* __restrict__ W1r,
                       const float* __restrict__ W2l, const float* __restrict__ W2r) {
    int i = blockIdx.x * blockDim.x + threadIdx.x;
    if (i < 128 * 128) {
        g_w1c[i] = W1l[i];
        g_w1c[128 * 128 + i] = W1r[i];
    }
    if (i < 128 * 40) {
        int r = i / 40, c = i - r * 40;
        g_w2c[r * 80 + c] = W2l[i];
        g_w2c[r * 80 + 40 + c] = W2r[i];
    }
}

// ---------------- layer-1 scatter: agg1[dst] += x[src], cnt[dst]++ ----------------
// one warp per edge; lane handles 4 consecutive channels (float4 gather, 4 REDG)
__global__ void scatter1(const float* __restrict__ x, const void* __restrict__ ei) {
    int gt = blockIdx.x * blockDim.x + threadIdx.x;
    int e = gt >> 5;
    int lane = gt & 31;
    if (e >= NE) return;
    const int is64 = g_is64;
    int src = edge_at(ei, e, is64);
    int dst = edge_at(ei, (long long)NE + e, is64);
    float4 v = ((const float4*)(x + (size_t)src * 128))[lane];
    float* a = g_agg1 + (size_t)dst * 128 + lane * 4;
    atomicAdd(a + 0, v.x);
    atomicAdd(a + 1, v.y);
    atomicAdd(a + 2, v.z);
    atomicAdd(a + 3, v.w);
    if (lane == 0) atomicAdd(g_cnt + dst, 1.0f);
}

// ---------------- normalize: agg1 /= max(cnt,1) ----------------
__global__ void norm1() {
    int i = blockIdx.x * blockDim.x + threadIdx.x; // NN*32 float4s
    if (i >= NN * 32) return;
    float inv = 1.0f / fmaxf(g_cnt[i >> 5], 1.0f);
    float4 v = ((float4*)g_agg1)[i];
    v.x *= inv; v.y *= inv; v.z *= inv; v.w *= inv;
    ((float4*)g_agg1)[i] = v;
}

// ---------------- register-tiled SGEMM ----------------
// C[M,N] = [A0 | A1](M x K, split at k=128, both lda=128) @ B(K x N row-major)
// epilogue: RELU -> C = relu(C + bias[col]); else raw store.
template <int K, int N, bool RELU>
__global__ __launch_bounds__(256) void sgemm(
    int M, const float* __restrict__ A0, const float* __restrict__ A1,
    const float* __restrict__ B, const float* __restrict__ bias,
    float* __restrict__ C) {
    constexpr int BM = 128, BN = 128, BK = 8, TM = 8, TN = 8;
    __shared__ float As[BK][BM]; // A transposed in smem
    __shared__ float Bs[BK][BN];
    const int tid = threadIdx.x;
    const int rowBase = blockIdx.y * BM;
    const int colBase = blockIdx.x * BN;
    const int trow = (tid >> 4) * TM;
    const int tcol = (tid & 15) * TN;
    const int aRow = tid >> 1;
    const int aCol = (tid & 1) << 2;
    const int bRow = tid >> 5;
    const int bCol = (tid & 31) << 2;

    float acc[TM][TN];
#pragma unroll
    for (int i = 0; i < TM; i++)
#pragma unroll
        for (int j = 0; j < TN; j++) acc[i][j] = 0.f;

    for (int k0 = 0; k0 < K; k0 += BK) {
        // ---- A tile (transposed store) ----
        float4 av = make_float4(0.f, 0.f, 0.f, 0.f);
        {
            int gr = rowBase + aRow;
            if (gr < M) {
                int gc = k0 + aCol;
                const float* Ap = (gc < 128)
                                      ? (A0 + (size_t)gr * 128 + gc)
                                      : (A1 + (size_t)gr * 128 + (gc - 128));
                av = *(const float4*)Ap;
            }
        }
        As[aCol + 0][aRow] = av.x;
        As[aCol + 1][aRow] = av.y;
        As[aCol + 2][aRow] = av.z;
        As[aCol + 3][aRow] = av.w;
        // ---- B tile ----
        {
            float4 bv = make_float4(0.f, 0.f, 0.f, 0.f);
            int gc = colBase + bCol;
            if (gc < N) bv = *(const float4*)(B + (size_t)(k0 + bRow) * N + gc);
            *(float4*)&Bs[bRow][bCol] = bv;
        }
        __syncthreads();
#pragma unroll
        for (int kk = 0; kk < BK; kk++) {
            float ra[TM], rb[TN];
            *(float4*)&ra[0] = *(const float4*)&As[kk][trow];
            *(float4*)&ra[4] = *(const float4*)&As[kk][trow + 4];
            *(float4*)&rb[0] = *(const float4*)&Bs[kk][tcol];
            *(float4*)&rb[4] = *(const float4*)&Bs[kk][tcol + 4];
#pragma unroll
            for (int i = 0; i < TM; i++)
#pragma unroll
                for (int j = 0; j < TN; j++) acc[i][j] += ra[i] * rb[j];
        }
        __syncthreads();
    }
    // ---- epilogue ----
#pragma unroll
    for (int i = 0; i < TM; i++) {
        int gr = rowBase + trow + i;
        if (gr >= M) continue;
#pragma unroll
        for (int j = 0; j < TN; j += 4) {
            int gc = colBase + tcol + j;
            if (gc >= N) continue; // gc % 4 == 0, N % 4 == 0 -> full float4 in range
            float4 o;
            o.x = acc[i][j + 0];
            o.y = acc[i][j + 1];
            o.z = acc[i][j + 2];
            o.w = acc[i][j + 3];
            if (RELU) {
                o.x = fmaxf(o.x + bias[gc + 0], 0.f);
                o.y = fmaxf(o.y + bias[gc + 1], 0.f);
                o.z = fmaxf(o.z + bias[gc + 2], 0.f);
                o.w = fmaxf(o.w + bias[gc + 3], 0.f);
            }
            *(float4*)(C + (size_t)gr * N + gc) = o;
        }
    }
}

// ---------------- layer-2 scatter: agg2[dst][0:40] += tr[src][0:40] ----------------
__global__ void scatter2(const void* __restrict__ ei) {
    long long i = (long long)blockIdx.x * blockDim.x + threadIdx.x; // NE*40 = 64M
    if (i >= (long long)NE * 40) return;
    int e = (int)(i / 40);
    int c = (int)(i - (long long)e * 40);
    const int is64 = g_is64;
    int src = edge_at(ei, e, is64);
    int dst = edge_at(ei, (long long)NE + e, is64);
    atomicAdd(g_agg2 + (size_t)dst * 40 + c, g_tr[(size_t)src * 80 + c]);
}

// ---------------- final: out = log_softmax(agg2/cnt + r + b2) ----------------
// one warp per node; lane covers channel lane, lanes 0..7 also cover 32+lane
__global__ void final_k(const float* __restrict__ b2, float* __restrict__ out) {
    int gt = blockIdx.x * blockDim.x + threadIdx.x;
    int n = gt >> 5;
    int lane = gt & 31;
    if (n >= NN) return;
    float inv = 1.0f / fmaxf(g_cnt[n], 1.0f);
    float e0 = g_agg2[(size_t)n * 40 + lane] * inv + g_tr[(size_t)n * 80 + 40 + lane] + b2[lane];
    float e1 = -3.4e38f;
    if (lane < 8)
        e1 = g_agg2[(size_t)n * 40 + 32 + lane] * inv + g_tr[(size_t)n * 80 + 72 + lane] + b2[32 + lane];
    float m = fmaxf(e0, e1);
#pragma unroll
    for (int o = 16; o > 0; o >>= 1) m = fmaxf(m, __shfl_xor_sync(0xffffffffu, m, o));
    float s = expf(e0 - m) + ((lane < 8) ? expf(e1 - m) : 0.f);
#pragma unroll
    for (int o = 16; o > 0; o >>= 1) s += __shfl_xor_sync(0xffffffffu, s, o);
    float lse = m + logf(s);
    out[(size_t)n * 40 + lane] = e0 - lse;
    if (lane < 8) out[(size_t)n * 40 + 32 + lane] = e1 - lse;
}

// ---------------- launch ----------------
extern "C" void kernel_launch(void* const* d_in, const int* in_sizes, int n_in,
                              void* d_out, int out_size) {
    const float* x      = (const float*)d_in[0];
    const void* ei      = d_in[1];            // int32 or int64 -> probed on device
    const float* W1l    = (const float*)d_in[2];
    const float* W1r    = (const float*)d_in[3];
    const float* b1     = (const float*)d_in[4];
    const float* W2l    = (const float*)d_in[5];
    const float* W2r    = (const float*)d_in[6];
    const float* b2     = (const float*)d_in[7];
    float* out          = (float*)d_out;

    float *agg1, *h, *tr, *w1c, *w2c;
    cudaGetSymbolAddress((void**)&agg1, g_agg1);
    cudaGetSymbolAddress((void**)&h, g_h);
    cudaGetSymbolAddress((void**)&tr, g_tr);
    cudaGetSymbolAddress((void**)&w1c, g_w1c);
    cudaGetSymbolAddress((void**)&w2c, g_w2c);

    const int mtiles = (NN + 127) / 128; // 782

    probe_k<<<1, 64>>>((const int*)ei);
    zero_k<<<(NN * 32 + 255) / 256, 256>>>();
    prep_w<<<64, 256>>>(W1l, W1r, W2l, W2r);
    scatter1<<<(NE * 32) / 256, 256>>>(x, ei);          // 200000 blocks
    norm1<<<(NN * 32 + 255) / 256, 256>>>();
    sgemm<256, 128, true><<<dim3(1, mtiles), 256>>>(NN, agg1, x, w1c, b1, h);
    sgemm<128, 80, false><<<dim3(1, mtiles), 256>>>(NN, h, h, w2c, nullptr, tr);
    scatter2<<<(int)(((long long)NE * 40 + 255) / 256), 256>>>(ei); // 250000 blocks
    final_k<<<(NN * 32 + 255) / 256, 256>>>(b2, out);   // 12500 blocks
}

// round 7
// speedup vs baseline: 2.2529x; 2.2529x over previous
#include <cuda_runtime.h>
#include <math.h>

#define NN 100000
#define NE 1600000
#define NB 98  // ceil(NN/1024) scan blocks

// ---------------- scratch (static __device__, no allocation) ----------------
__device__ __align__(16) float g_agg1[(size_t)NN * 128]; // layer-1 neighbor means
__device__ __align__(16) float g_h[(size_t)NN * 128];    // layer-1 output (relu)
__device__ __align__(16) float g_tr[(size_t)NN * 80];    // [h@W2l | h@W2r] per node
__device__ __align__(16) float g_w1c[256 * 128];         // [W1l ; W1r] stacked along K
__device__ __align__(16) float g_w2c[128 * 80];          // [W2l | W2r] stacked along N
__device__ int g_src[NE];       // edge src (int32)
__device__ int g_dst[NE];       // edge dst (int32)
__device__ int g_csr[NE];       // src ids grouped by dst
__device__ int g_deg[NN];       // in-degree
__device__ int g_rowstart[NN];  // CSR row offsets (exclusive scan of deg)
__device__ int g_cursor[NN];    // fill cursors
__device__ int g_scan[NN];      // per-block inclusive scans
__device__ int g_bsum[NB];      // block sums -> inclusive scanned
__device__ int g_is64;          // edge_index dtype flag

// ---------------- probe edge_index dtype ----------------
// int64 (LE, values < 1e5) => every odd int32 word is 0. Deterministic for a
// fixed dataset.
__global__ void probe_k(const int* __restrict__ ei32) {
    if (threadIdx.x != 0 || blockIdx.x != 0) return;
    int is64 = 1;
    for (int i = 1; i < 256; i += 2)
        if (ei32[i] != 0) { is64 = 0; break; }
    g_is64 = is64;
}

// ---------------- zero int scratch ----------------
__global__ void zero_k() {
    int i = blockIdx.x * blockDim.x + threadIdx.x;
    if (i < NN) { g_deg[i] = 0; g_cursor[i] = 0; }
}

// ---------------- edge convert + degree histogram ----------------
__global__ void convert_k(const void* __restrict__ ei) {
    int e = blockIdx.x * blockDim.x + threadIdx.x;
    if (e >= NE) return;
    int src, dst;
    if (g_is64) {
        src = (int)((const long long*)ei)[e];
        dst = (int)((const long long*)ei)[(long long)NE + e];
    } else {
        src = ((const int*)ei)[e];
        dst = ((const int*)ei)[NE + e];
    }
    g_src[e] = src;
    g_dst[e] = dst;
    atomicAdd(&g_deg[dst], 1);
}

// ---------------- prefix scan (3 kernels) ----------------
__global__ __launch_bounds__(1024) void scan1_k() {
    __shared__ int s[1024];
    int t = threadIdx.x;
    int i = blockIdx.x * 1024 + t;
    int v = (i < NN) ? g_deg[i] : 0;
    s[t] = v;
    __syncthreads();
#pragma unroll
    for (int off = 1; off < 1024; off <<= 1) {
        int a = (t >= off) ? s[t - off] : 0;
        __syncthreads();
        s[t] += a;
        __syncthreads();
    }
    if (i < NN) g_scan[i] = s[t];
    if (t == 1023) g_bsum[blockIdx.x] = s[t];
}
__global__ void scan2_k() {
    if (threadIdx.x != 0) return;
    int acc = 0;
    for (int b = 0; b < NB; b++) { acc += g_bsum[b]; g_bsum[b] = acc; }
}
__global__ void scan3_k() {
    int i = blockIdx.x * blockDim.x + threadIdx.x;
    if (i >= NN) return;
    int b = i >> 10;
    int base = (b > 0) ? g_bsum[b - 1] : 0;
    g_rowstart[i] = base + g_scan[i] - g_deg[i]; // exclusive
}

// ---------------- CSR fill ----------------
__global__ void fill_k() {
    int e = blockIdx.x * blockDim.x + threadIdx.x;
    if (e >= NE) return;
    int d = g_dst[e];
    int pos = g_rowstart[d] + atomicAdd(&g_cursor[d], 1);
    g_csr[pos] = g_src[e];
}

// ---------------- layer-1 gather-mean: agg1[n] = mean_{s in N(n)} x[s] ----------------
// one warp per node; lane owns 4 consecutive channels (float4)
__global__ void agg1_k(const float* __restrict__ x) {
    int gt = blockIdx.x * blockDim.x + threadIdx.x;
    int n = gt >> 5;
    int lane = gt & 31;
    if (n >= NN) return;
    int start = g_rowstart[n];
    int deg = g_deg[n];
    float4 acc = make_float4(0.f, 0.f, 0.f, 0.f);
    int i = 0;
    for (; i + 1 < deg; i += 2) {
        int s0 = __ldg(g_csr + start + i);
        int s1 = __ldg(g_csr + start + i + 1);
        float4 v0 = ((const float4*)(x + (size_t)s0 * 128))[lane];
        float4 v1 = ((const float4*)(x + (size_t)s1 * 128))[lane];
        acc.x += v0.x + v1.x; acc.y += v0.y + v1.y;
        acc.z += v0.z + v1.z; acc.w += v0.w + v1.w;
    }
    if (i < deg) {
        int s0 = __ldg(g_csr + start + i);
        float4 v0 = ((const float4*)(x + (size_t)s0 * 128))[lane];
        acc.x += v0.x; acc.y += v0.y; acc.z += v0.z; acc.w += v0.w;
    }
    float inv = 1.0f / fmaxf((float)deg, 1.0f);
    acc.x *= inv; acc.y *= inv; acc.z *= inv; acc.w *= inv;
    ((float4*)(g_agg1 + (size_t)n * 128))[lane] = acc;
}

// ---------------- pack weight matrices ----------------
__global__ void prep_w(const float* __restrict__ W1l, const float* __restrict__ W1r,
                       const float* __restrict__ W2l, const float* __restrict__ W2r) {
    int i = blockIdx.x * blockDim.x + threadIdx.x;
    if (i < 128 * 128) {
        g_w1c[i] = W1l[i];
        g_w1c[128 * 128 + i] = W1r[i];
    }
    if (i < 128 * 40) {
        int r = i / 40, c = i - r * 40;
        g_w2c[r * 80 + c] = W2l[i];
        g_w2c[r * 80 + 40 + c] = W2r[i];
    }
}

// ---------------- register-tiled SGEMM ----------------
// C[M,N] = [A0 | A1](M x K, split at k=128, both lda=128) @ B(K x N row-major)
template <int K, int N, bool RELU>
__global__ __launch_bounds__(256) void sgemm(
    int M, const float* __restrict__ A0, const float* __restrict__ A1,
    const float* __restrict__ B, const float* __restrict__ bias,
    float* __restrict__ C) {
    constexpr int BM = 128, BN = 128, BK = 8, TM = 8, TN = 8;
    __shared__ float As[BK][BM];
    __shared__ float Bs[BK][BN];
    const int tid = threadIdx.x;
    const int rowBase = blockIdx.y * BM;
    const int colBase = blockIdx.x * BN;
    const int trow = (tid >> 4) * TM;
    const int tcol = (tid & 15) * TN;
    const int aRow = tid >> 1;
    const int aCol = (tid & 1) << 2;
    const int bRow = tid >> 5;
    const int bCol = (tid & 31) << 2;

    float acc[TM][TN];
#pragma unroll
    for (int i = 0; i < TM; i++)
#pragma unroll
        for (int j = 0; j < TN; j++) acc[i][j] = 0.f;

    for (int k0 = 0; k0 < K; k0 += BK) {
        float4 av = make_float4(0.f, 0.f, 0.f, 0.f);
        {
            int gr = rowBase + aRow;
            if (gr < M) {
                int gc = k0 + aCol;
                const float* Ap = (gc < 128)
                                      ? (A0 + (size_t)gr * 128 + gc)
                                      : (A1 + (size_t)gr * 128 + (gc - 128));
                av = *(const float4*)Ap;
            }
        }
        As[aCol + 0][aRow] = av.x;
        As[aCol + 1][aRow] = av.y;
        As[aCol + 2][aRow] = av.z;
        As[aCol + 3][aRow] = av.w;
        {
            float4 bv = make_float4(0.f, 0.f, 0.f, 0.f);
            int gc = colBase + bCol;
            if (gc < N) bv = *(const float4*)(B + (size_t)(k0 + bRow) * N + gc);
            *(float4*)&Bs[bRow][bCol] = bv;
        }
        __syncthreads();
#pragma unroll
        for (int kk = 0; kk < BK; kk++) {
            float ra[TM], rb[TN];
            *(float4*)&ra[0] = *(const float4*)&As[kk][trow];
            *(float4*)&ra[4] = *(const float4*)&As[kk][trow + 4];
            *(float4*)&rb[0] = *(const float4*)&Bs[kk][tcol];
            *(float4*)&rb[4] = *(const float4*)&Bs[kk][tcol + 4];
#pragma unroll
            for (int i = 0; i < TM; i++)
#pragma unroll
                for (int j = 0; j < TN; j++) acc[i][j] += ra[i] * rb[j];
        }
        __syncthreads();
    }
#pragma unroll
    for (int i = 0; i < TM; i++) {
        int gr = rowBase + trow + i;
        if (gr >= M) continue;
#pragma unroll
        for (int j = 0; j < TN; j += 4) {
            int gc = colBase + tcol + j;
            if (gc >= N) continue;
            float4 o;
            o.x = acc[i][j + 0];
            o.y = acc[i][j + 1];
            o.z = acc[i][j + 2];
            o.w = acc[i][j + 3];
            if (RELU) {
                o.x = fmaxf(o.x + bias[gc + 0], 0.f);
                o.y = fmaxf(o.y + bias[gc + 1], 0.f);
                o.z = fmaxf(o.z + bias[gc + 2], 0.f);
                o.w = fmaxf(o.w + bias[gc + 3], 0.f);
            }
            *(float4*)(C + (size_t)gr * N + gc) = o;
        }
    }
}

// ---------------- fused layer-2 gather-mean + root + bias + log_softmax ----------------
// one warp per node; lanes 0..19 each own 2 channels (float2) of the 40
__global__ void final_k(const float* __restrict__ b2, float* __restrict__ out) {
    int gt = blockIdx.x * blockDim.x + threadIdx.x;
    int n = gt >> 5;
    int lane = gt & 31;
    if (n >= NN) return;
    int start = g_rowstart[n];
    int deg = g_deg[n];
    int c = lane * 2;
    float2 acc = make_float2(0.f, 0.f);
    if (lane < 20) {
        for (int i = 0; i < deg; i++) {
            int s = __ldg(g_csr + start + i);
            float2 v = *(const float2*)(g_tr + (size_t)s * 80 + c);
            acc.x += v.x;
            acc.y += v.y;
        }
    }
    float inv = 1.0f / fmaxf((float)deg, 1.0f);
    float e0 = -3.4e38f, e1 = -3.4e38f;
    if (lane < 20) {
        e0 = acc.x * inv + g_tr[(size_t)n * 80 + 40 + c] + b2[c];
        e1 = acc.y * inv + g_tr[(size_t)n * 80 + 41 + c] + b2[c + 1];
    }
    float m = fmaxf(e0, e1);
#pragma unroll
    for (int o = 16; o > 0; o >>= 1) m = fmaxf(m, __shfl_xor_sync(0xffffffffu, m, o));
    float s = (lane < 20) ? (expf(e0 - m) + expf(e1 - m)) : 0.f;
#pragma unroll
    for (int o = 16; o > 0; o >>= 1) s += __shfl_xor_sync(0xffffffffu, s, o);
    float lse = m + logf(s);
    if (lane < 20) {
        float2 o2;
        o2.x = e0 - lse;
        o2.y = e1 - lse;
        *(float2*)(out + (size_t)n * 40 + c) = o2;
    }
}

// ---------------- launch ----------------
extern "C" void kernel_launch(void* const* d_in, const int* in_sizes, int n_in,
                              void* d_out, int out_size) {
    const float* x   = (const float*)d_in[0];
    const void* ei   = d_in[1]; // int32 or int64, probed on device
    const float* W1l = (const float*)d_in[2];
    const float* W1r = (const float*)d_in[3];
    const float* b1  = (const float*)d_in[4];
    const float* W2l = (const float*)d_in[5];
    const float* W2r = (const float*)d_in[6];
    const float* b2  = (const float*)d_in[7];
    float* out       = (float*)d_out;

    float *agg1, *h, *tr, *w1c, *w2c;
    cudaGetSymbolAddress((void**)&agg1, g_agg1);
    cudaGetSymbolAddress((void**)&h, g_h);
    cudaGetSymbolAddress((void**)&tr, g_tr);
    cudaGetSymbolAddress((void**)&w1c, g_w1c);
    cudaGetSymbolAddress((void**)&w2c, g_w2c);

    const int mtiles = (NN + 127) / 128; // 782

    probe_k<<<1, 32>>>((const int*)ei);
    zero_k<<<(NN + 255) / 256, 256>>>();
    prep_w<<<64, 256>>>(W1l, W1r, W2l, W2r);
    convert_k<<<(NE + 255) / 256, 256>>>(ei);
    scan1_k<<<NB, 1024>>>();
    scan2_k<<<1, 32>>>();
    scan3_k<<<(NN + 255) / 256, 256>>>();
    fill_k<<<(NE + 255) / 256, 256>>>();
    agg1_k<<<(NN * 32 + 255) / 256, 256>>>(x);                      // 12500 blocks
    sgemm<256, 128, true><<<dim3(1, mtiles), 256>>>(NN, agg1, x, w1c, b1, h);
    sgemm<128, 80, false><<<dim3(1, mtiles), 256>>>(NN, h, h, w2c, nullptr, tr);
    final_k<<<(NN * 32 + 255) / 256, 256>>>(b2, out);               // 12500 blocks
}

// round 9
// speedup vs baseline: 3.5859x; 1.5917x over previous
#include <cuda_runtime.h>
#include <cuda_bf16.h>
#include <math.h>
#include <stdint.h>

#define NN 100000
#define NE 1600000
#define NB 98  // ceil(NN/1024) scan blocks

// ---------------- scratch (static __device__, no allocation) ----------------
__device__ __align__(16) float g_agg1[(size_t)NN * 128]; // layer-1 neighbor means
__device__ __align__(16) float g_h[(size_t)NN * 128];    // layer-1 output (relu)
__device__ __align__(16) float g_tr[(size_t)NN * 80];    // [h@W2l | h@W2r] per node
// weights pre-transposed to [N][K] (K contiguous) and split into bf16 hi/lo
__device__ __align__(16) unsigned short g_w1h[128 * 256];
__device__ __align__(16) unsigned short g_w1lo[128 * 256];
__device__ __align__(16) unsigned short g_w2h[80 * 128];
__device__ __align__(16) unsigned short g_w2lo[80 * 128];
__device__ int g_src[NE];
__device__ int g_dst[NE];
__device__ int g_csr[NE];
__device__ int g_deg[NN];
__device__ int g_rowstart[NN];
__device__ int g_cursor[NN];
__device__ int g_scan[NN];
__device__ int g_bsum[NB];
__device__ int g_is64;

// ---------------- PTX helpers (sm_80-era, valid at compute_100) ----------------
static __device__ __forceinline__ uint32_t s2u(const void* p) {
    uint32_t a;
    asm("{ .reg .u64 t; cvta.to.shared.u64 t, %1; cvt.u32.u64 %0, t; }" : "=r"(a) : "l"(p));
    return a;
}
#define LDMX4(r0, r1, r2, r3, addr)                                             \
    asm volatile("ldmatrix.sync.aligned.m8n8.x4.shared.b16 {%0,%1,%2,%3}, [%4];" \
                 : "=r"(r0), "=r"(r1), "=r"(r2), "=r"(r3) : "r"(addr))
#define MMA16816(d, a0, a1, a2, a3, b0, b1)                                     \
    asm volatile("mma.sync.aligned.m16n8k16.row.col.f32.bf16.bf16.f32 "          \
                 "{%0,%1,%2,%3},{%4,%5,%6,%7},{%8,%9},{%0,%1,%2,%3};"            \
                 : "+f"((d)[0]), "+f"((d)[1]), "+f"((d)[2]), "+f"((d)[3])        \
                 : "r"(a0), "r"(a1), "r"(a2), "r"(a3), "r"(b0), "r"(b1))

// ---------------- probe edge_index dtype ----------------
__global__ void probe_k(const int* __restrict__ ei32) {
    if (threadIdx.x != 0 || blockIdx.x != 0) return;
    int is64 = 1;
    for (int i = 1; i < 256; i += 2)
        if (ei32[i] != 0) { is64 = 0; break; }
    g_is64 = is64;
}

// ---------------- zero int scratch ----------------
__global__ void zero_k() {
    int i = blockIdx.x * blockDim.x + threadIdx.x;
    if (i < NN) { g_deg[i] = 0; g_cursor[i] = 0; }
}

// ---------------- edge convert + degree histogram ----------------
__global__ void convert_k(const void* __restrict__ ei) {
    int e = blockIdx.x * blockDim.x + threadIdx.x;
    if (e >= NE) return;
    int src, dst;
    if (g_is64) {
        src = (int)((const long long*)ei)[e];
        dst = (int)((const long long*)ei)[(long long)NE + e];
    } else {
        src = ((const int*)ei)[e];
        dst = ((const int*)ei)[NE + e];
    }
    g_src[e] = src;
    g_dst[e] = dst;
    atomicAdd(&g_deg[dst], 1);
}

// ---------------- prefix scan ----------------
__global__ __launch_bounds__(1024) void scan1_k() {
    __shared__ int s[1024];
    int t = threadIdx.x;
    int i = blockIdx.x * 1024 + t;
    int v = (i < NN) ? g_deg[i] : 0;
    s[t] = v;
    __syncthreads();
#pragma unroll
    for (int off = 1; off < 1024; off <<= 1) {
        int a = (t >= off) ? s[t - off] : 0;
        __syncthreads();
        s[t] += a;
        __syncthreads();
    }
    if (i < NN) g_scan[i] = s[t];
    if (t == 1023) g_bsum[blockIdx.x] = s[t];
}
__global__ void scan2_k() {
    if (threadIdx.x != 0) return;
    int acc = 0;
    for (int b = 0; b < NB; b++) { acc += g_bsum[b]; g_bsum[b] = acc; }
}
__global__ void scan3_k() {
    int i = blockIdx.x * blockDim.x + threadIdx.x;
    if (i >= NN) return;
    int b = i >> 10;
    int base = (b > 0) ? g_bsum[b - 1] : 0;
    g_rowstart[i] = base + g_scan[i] - g_deg[i];
}

// ---------------- CSR fill ----------------
__global__ void fill_k() {
    int e = blockIdx.x * blockDim.x + threadIdx.x;
    if (e >= NE) return;
    int d = g_dst[e];
    int pos = g_rowstart[d] + atomicAdd(&g_cursor[d], 1);
    g_csr[pos] = g_src[e];
}

// ---------------- layer-1 gather-mean ----------------
__global__ void agg1_k(const float* __restrict__ x) {
    int gt = blockIdx.x * blockDim.x + threadIdx.x;
    int n = gt >> 5;
    int lane = gt & 31;
    if (n >= NN) return;
    int start = g_rowstart[n];
    int deg = g_deg[n];
    float4 acc = make_float4(0.f, 0.f, 0.f, 0.f);
    int i = 0;
    for (; i + 1 < deg; i += 2) {
        int s0 = __ldg(g_csr + start + i);
        int s1 = __ldg(g_csr + start + i + 1);
        float4 v0 = ((const float4*)(x + (size_t)s0 * 128))[lane];
        float4 v1 = ((const float4*)(x + (size_t)s1 * 128))[lane];
        acc.x += v0.x + v1.x; acc.y += v0.y + v1.y;
        acc.z += v0.z + v1.z; acc.w += v0.w + v1.w;
    }
    if (i < deg) {
        int s0 = __ldg(g_csr + start + i);
        float4 v0 = ((const float4*)(x + (size_t)s0 * 128))[lane];
        acc.x += v0.x; acc.y += v0.y; acc.z += v0.z; acc.w += v0.w;
    }
    float inv = 1.0f / fmaxf((float)deg, 1.0f);
    acc.x *= inv; acc.y *= inv; acc.z *= inv; acc.w *= inv;
    ((float4*)(g_agg1 + (size_t)n * 128))[lane] = acc;
}

// ---------------- pack + split weight matrices -> [N][K] bf16 hi/lo ----------------
static __device__ __forceinline__ void split1(float v, unsigned short& h, unsigned short& l) {
    uint32_t u = __float_as_uint(v);
    h = (unsigned short)(u >> 16);                      // truncated bf16
    float hf = __uint_as_float(u & 0xFFFF0000u);
    l = __bfloat16_as_ushort(__float2bfloat16(v - hf)); // rn residual
}
__global__ void prep_w(const float* __restrict__ W1l, const float* __restrict__ W1r,
                       const float* __restrict__ W2l, const float* __restrict__ W2r) {
    int i = blockIdx.x * blockDim.x + threadIdx.x;
    if (i < 128 * 256) { // w1: n = i/256, k = i%256
        int n = i >> 8, k = i & 255;
        float v = (k < 128) ? W1l[k * 128 + n] : W1r[(k - 128) * 128 + n];
        split1(v, g_w1h[i], g_w1lo[i]);
    }
    if (i < 80 * 128) { // w2: n = i/128, k = i%128
        int n = i >> 7, k = i & 127;
        float v = (n < 40) ? W2l[k * 40 + n] : W2r[k * 40 + (n - 40)];
        split1(v, g_w2h[i], g_w2lo[i]);
    }
}

// ---------------- mma.sync split-bf16 GEMM ----------------
// C[M,N] = [A0 | A1](M x KT fp32, split at col 128, both lda=128) @ B(KT x N),
// B given as [N][KT] bf16 hi/lo. D += Ah*Bh + Ah*Bl + Al*Bh (fp32 accum).
// Block: 128 rows x full N; 8 warps, each warp = 16 rows x N.
template <int N, int KT, bool RELU>
__global__ __launch_bounds__(256) void gemm_mma(
    int M, const float* __restrict__ A0, const float* __restrict__ A1,
    const unsigned short* __restrict__ Bh, const unsigned short* __restrict__ Bl,
    const float* __restrict__ bias, float* __restrict__ C) {
    constexpr int NT8 = N / 8;   // n8 tiles (16 or 10) — even
    constexpr int KC = KT / 32;  // 32-wide k-chunks
    constexpr int ST = 40;       // SMEM row stride in ushorts (padded, conflict-free)
    __shared__ unsigned short sAh[128 * ST], sAl[128 * ST];
    __shared__ unsigned short sBh[N * ST], sBl[N * ST];

    const int tid = threadIdx.x;
    const int wid = tid >> 5, lane = tid & 31;
    const int rowBase = blockIdx.x * 128;

    float acc[NT8][4];
#pragma unroll
    for (int t = 0; t < NT8; t++)
#pragma unroll
        for (int q = 0; q < 4; q++) acc[t][q] = 0.f;

    const int arow = tid >> 1;          // A smem row this thread fills
    const int ach = (tid & 1) * 16;     // col half (0 or 16)
    const int gr_a = rowBase + arow;

    for (int c = 0; c < KC; c++) {
        const int gk = c * 32;
        // ---- A chunk: fp32 -> bf16 hi/lo ----
        const float* Ap = (gk < 128) ? (A0 + (size_t)gr_a * 128 + gk + ach)
                                     : (A1 + (size_t)gr_a * 128 + (gk - 128) + ach);
#pragma unroll
        for (int i = 0; i < 4; i++) {
            float4 v = (gr_a < M) ? *(const float4*)(Ap + i * 4)
                                  : make_float4(0.f, 0.f, 0.f, 0.f);
            uint32_t ux = __float_as_uint(v.x), uy = __float_as_uint(v.y);
            uint32_t uz = __float_as_uint(v.z), uw = __float_as_uint(v.w);
            uint2 hv, lv;
            hv.x = (ux >> 16) | (uy & 0xFFFF0000u);
            hv.y = (uz >> 16) | (uw & 0xFFFF0000u);
            unsigned short l0 = __bfloat16_as_ushort(
                __float2bfloat16(v.x - __uint_as_float(ux & 0xFFFF0000u)));
            unsigned short l1 = __bfloat16_as_ushort(
                __float2bfloat16(v.y - __uint_as_float(uy & 0xFFFF0000u)));
            unsigned short l2 = __bfloat16_as_ushort(
                __float2bfloat16(v.z - __uint_as_float(uz & 0xFFFF0000u)));
            unsigned short l3 = __bfloat16_as_ushort(
                __float2bfloat16(v.w - __uint_as_float(uw & 0xFFFF0000u)));
            lv.x = (uint32_t)l0 | ((uint32_t)l1 << 16);
            lv.y = (uint32_t)l2 | ((uint32_t)l3 << 16);
            *(uint2*)&sAh[arow * ST + ach + i * 4] = hv;
            *(uint2*)&sAl[arow * ST + ach + i * 4] = lv;
        }
        // ---- B chunk: [N][32] bf16 hi/lo straight copy ----
        for (int idx = tid; idx < N * 4; idx += 256) {
            int n = idx >> 2, q = idx & 3;
            *(uint4*)&sBh[n * ST + q * 8] = *(const uint4*)(Bh + (size_t)n * KT + gk + q * 8);
            *(uint4*)&sBl[n * ST + q * 8] = *(const uint4*)(Bl + (size_t)n * KT + gk + q * 8);
        }
        __syncthreads();
        // ---- 2 k-steps of 16 ----
#pragma unroll
        for (int ks = 0; ks < 2; ks++) {
            const int kb = ks * 16;
            // A fragments (m16k16): lanes 0-7 m0-7@k0, 8-15 m8-15@k0,
            //                       16-23 m0-7@k8, 24-31 m8-15@k8
            const int am = wid * 16 + (lane & 7) + ((lane >> 3) & 1) * 8;
            const int ak = kb + (lane >> 4) * 8;
            uint32_t ah0, ah1, ah2, ah3, al0, al1, al2, al3;
            {
                uint32_t addr = s2u(&sAh[am * ST + ak]);
                LDMX4(ah0, ah1, ah2, ah3, addr);
                addr = s2u(&sAl[am * ST + ak]);
                LDMX4(al0, al1, al2, al3, addr);
            }
            // B fragments, 2 n8-tiles per x4 ldmatrix:
            // lanes 0-7 n0-7@k0, 8-15 n0-7@k8, 16-23 n8-15@k0, 24-31 n8-15@k8
            const int bn = (lane & 7) + (lane >> 4) * 8;
            const int bk = kb + ((lane >> 3) & 1) * 8;
#pragma unroll
            for (int p = 0; p < NT8 / 2; p++) {
                uint32_t bh0, bh1, bh2, bh3, bl0_, bl1_, bl2_, bl3_;
                uint32_t addr = s2u(&sBh[(p * 16 + bn) * ST + bk]);
                LDMX4(bh0, bh1, bh2, bh3, addr);
                addr = s2u(&sBl[(p * 16 + bn) * ST + bk]);
                LDMX4(bl0_, bl1_, bl2_, bl3_, addr);
                MMA16816(acc[2 * p + 0], ah0, ah1, ah2, ah3, bh0, bh1);
                MMA16816(acc[2 * p + 0], ah0, ah1, ah2, ah3, bl0_, bl1_);
                MMA16816(acc[2 * p + 0], al0, al1, al2, al3, bh0, bh1);
                MMA16816(acc[2 * p + 1], ah0, ah1, ah2, ah3, bh2, bh3);
                MMA16816(acc[2 * p + 1], ah0, ah1, ah2, ah3, bl2_, bl3_);
                MMA16816(acc[2 * p + 1], al0, al1, al2, al3, bh2, bh3);
            }
        }
        __syncthreads();
    }
    // ---- epilogue: c0,c1 -> (row = lane>>2, cols 2*(lane&3)+{0,1}); c2,c3 -> row+8
    const int r0 = rowBase + wid * 16 + (lane >> 2);
    const int col0 = (lane & 3) * 2;
#pragma unroll
    for (int t = 0; t < NT8; t++) {
        int col = t * 8 + col0;
        float2 v0 = make_float2(acc[t][0], acc[t][1]);
        float2 v1 = make_float2(acc[t][2], acc[t][3]);
        if (RELU) {
            float b0v = __ldg(bias + col), b1v = __ldg(bias + col + 1);
            v0.x = fmaxf(v0.x + b0v, 0.f); v0.y = fmaxf(v0.y + b1v, 0.f);
            v1.x = fmaxf(v1.x + b0v, 0.f); v1.y = fmaxf(v1.y + b1v, 0.f);
        }
        if (r0 < M)     *(float2*)(C + (size_t)r0 * N + col) = v0;
        if (r0 + 8 < M) *(float2*)(C + (size_t)(r0 + 8) * N + col) = v1;
    }
}

// ---------------- fused layer-2 gather-mean + root + bias + log_softmax ----------------
__global__ void final_k(const float* __restrict__ b2, float* __restrict__ out) {
    int gt = blockIdx.x * blockDim.x + threadIdx.x;
    int n = gt >> 5;
    int lane = gt & 31;
    if (n >= NN) return;
    int start = g_rowstart[n];
    int deg = g_deg[n];
    int c = lane * 2;
    float2 acc = make_float2(0.f, 0.f);
    if (lane < 20) {
        for (int i = 0; i < deg; i++) {
            int s = __ldg(g_csr + start + i);
            float2 v = *(const float2*)(g_tr + (size_t)s * 80 + c);
            acc.x += v.x;
            acc.y += v.y;
        }
    }
    float inv = 1.0f / fmaxf((float)deg, 1.0f);
    float e0 = -3.4e38f, e1 = -3.4e38f;
    if (lane < 20) {
        e0 = acc.x * inv + g_tr[(size_t)n * 80 + 40 + c] + b2[c];
        e1 = acc.y * inv + g_tr[(size_t)n * 80 + 41 + c] + b2[c + 1];
    }
    float m = fmaxf(e0, e1);
#pragma unroll
    for (int o = 16; o > 0; o >>= 1) m = fmaxf(m, __shfl_xor_sync(0xffffffffu, m, o));
    float s = (lane < 20) ? (expf(e0 - m) + expf(e1 - m)) : 0.f;
#pragma unroll
    for (int o = 16; o > 0; o >>= 1) s += __shfl_xor_sync(0xffffffffu, s, o);
    float lse = m + logf(s);
    if (lane < 20) {
        float2 o2;
        o2.x = e0 - lse;
        o2.y = e1 - lse;
        *(float2*)(out + (size_t)n * 40 + c) = o2;
    }
}

// ---------------- launch ----------------
extern "C" void kernel_launch(void* const* d_in, const int* in_sizes, int n_in,
                              void* d_out, int out_size) {
    const float* x   = (const float*)d_in[0];
    const void* ei   = d_in[1];
    const float* W1l = (const float*)d_in[2];
    const float* W1r = (const float*)d_in[3];
    const float* b1  = (const float*)d_in[4];
    const float* W2l = (const float*)d_in[5];
    const float* W2r = (const float*)d_in[6];
    const float* b2  = (const float*)d_in[7];
    float* out       = (float*)d_out;

    float *agg1, *h, *tr;
    unsigned short *w1h, *w1lo, *w2h, *w2lo;
    cudaGetSymbolAddress((void**)&agg1, g_agg1);
    cudaGetSymbolAddress((void**)&h, g_h);
    cudaGetSymbolAddress((void**)&tr, g_tr);
    cudaGetSymbolAddress((void**)&w1h, g_w1h);
    cudaGetSymbolAddress((void**)&w1lo, g_w1lo);
    cudaGetSymbolAddress((void**)&w2h, g_w2h);
    cudaGetSymbolAddress((void**)&w2lo, g_w2lo);

    const int mtiles = (NN + 127) / 128; // 782

    probe_k<<<1, 32>>>((const int*)ei);
    zero_k<<<(NN + 255) / 256, 256>>>();
    prep_w<<<128, 256>>>(W1l, W1r, W2l, W2r);
    convert_k<<<(NE + 255) / 256, 256>>>(ei);
    scan1_k<<<NB, 1024>>>();
    scan2_k<<<1, 32>>>();
    scan3_k<<<(NN + 255) / 256, 256>>>();
    fill_k<<<(NE + 255) / 256, 256>>>();
    agg1_k<<<(NN * 32 + 255) / 256, 256>>>(x);
    gemm_mma<128, 256, true><<<mtiles, 256>>>(NN, agg1, x, w1h, w1lo, b1, h);
    gemm_mma<80, 128, false><<<mtiles, 256>>>(NN, h, h, w2h, w2lo, nullptr, tr);
    final_k<<<(NN * 32 + 255) / 256, 256>>>(b2, out);
}